// round 1
// baseline (speedup 1.0000x reference)
#include <cuda_runtime.h>

#define BB 16
#define NN 2000
#define DD 128
#define OO 64
#define NL 3
#define NPAD 2048
#define BN (BB*NN)
#define NCH 16
#define CH 125
#define NP1 (NN+1)
#define HSS 20

__device__ float g_h[BN*DD];
__device__ float g_Wh[BN*DD];
__device__ float g_e1[BN];
__device__ float g_e2[BN];
__device__ float g_e2s[BB*NPAD];
__device__ int   g_perm[BB*NPAD];
__device__ float g_u1[BB*NN];
__device__ float g_u2[BB*NN];
__device__ float g_S1[BB*NP1*DD];
__device__ float g_P2[BB*NP1*DD];
__device__ float g_S1s[BB*NP1];
__device__ float g_P2s[BB*NP1];
__device__ float g_chF[BB*NCH*DD];
__device__ float g_chB[BB*NCH*DD];
__device__ float g_chFs[BB*NCH];
__device__ float g_chBs[BB*NCH];

__device__ __forceinline__ void fma16(float4 a, float4 b, float4 c, float4 d,
                                      float wv, float* acc) {
    acc[0]  = fmaf(a.x, wv, acc[0]);  acc[1]  = fmaf(a.y, wv, acc[1]);
    acc[2]  = fmaf(a.z, wv, acc[2]);  acc[3]  = fmaf(a.w, wv, acc[3]);
    acc[4]  = fmaf(b.x, wv, acc[4]);  acc[5]  = fmaf(b.y, wv, acc[5]);
    acc[6]  = fmaf(b.z, wv, acc[6]);  acc[7]  = fmaf(b.w, wv, acc[7]);
    acc[8]  = fmaf(c.x, wv, acc[8]);  acc[9]  = fmaf(c.y, wv, acc[9]);
    acc[10] = fmaf(c.z, wv, acc[10]); acc[11] = fmaf(c.w, wv, acc[11]);
    acc[12] = fmaf(d.x, wv, acc[12]); acc[13] = fmaf(d.y, wv, acc[13]);
    acc[14] = fmaf(d.z, wv, acc[14]); acc[15] = fmaf(d.w, wv, acc[15]);
}

__device__ __forceinline__ void gemm_inner(const float* __restrict__ M, const float* hs,
                                           int t, int ldm, float* acc) {
#pragma unroll 4
    for (int k = 0; k < DD; k++) {
        float wv = M[k*ldm + t];
        const float4* hp = (const float4*)(hs + k*HSS);
        fma16(hp[0], hp[1], hp[2], hp[3], wv, acc);
    }
}

__global__ void enc_kernel(const float* __restrict__ coords, const float* __restrict__ w0,
                           const float* __restrict__ b0, const float* __restrict__ w1,
                           const float* __restrict__ b1) {
    __shared__ float hs[DD*HSS];
    int t = threadIdx.x;
    int base = blockIdx.x * 16;
    float w00 = w0[t], w01 = w0[DD + t], bb = b0[t];
#pragma unroll
    for (int i = 0; i < 16; i++) {
        float cx = coords[(base + i) * 2 + 0];
        float cy = coords[(base + i) * 2 + 1];
        hs[t*HSS + i] = fmaxf(fmaf(cx, w00, fmaf(cy, w01, bb)), 0.f);
    }
    __syncthreads();
    float acc[16];
    float bv = b1[t];
#pragma unroll
    for (int i = 0; i < 16; i++) acc[i] = bv;
    gemm_inner(w1, hs, t, DD, acc);
#pragma unroll
    for (int i = 0; i < 16; i++) g_h[(size_t)(base + i)*DD + t] = acc[i];
}

__global__ void wh_kernel(const float* __restrict__ W) {
    __shared__ float hs[DD*HSS];
    int t = threadIdx.x;
    int base = blockIdx.x * 16;
#pragma unroll
    for (int i = 0; i < 16; i++) hs[t*HSS + i] = g_h[(size_t)(base + i)*DD + t];
    __syncthreads();
    float acc[16];
#pragma unroll
    for (int i = 0; i < 16; i++) acc[i] = 0.f;
    gemm_inner(W, hs, t, DD, acc);
#pragma unroll
    for (int i = 0; i < 16; i++) g_Wh[(size_t)(base + i)*DD + t] = acc[i];
}

__global__ void e_kernel(const float* __restrict__ a1, const float* __restrict__ a2) {
    int node = blockIdx.x * 8 + (threadIdx.x >> 5);
    int lane = threadIdx.x & 31;
    const float* wh = g_Wh + (size_t)node * DD;
    float s1 = 0.f, s2 = 0.f;
#pragma unroll
    for (int k = lane; k < DD; k += 32) {
        float w = wh[k];
        s1 = fmaf(w, a1[k], s1);
        s2 = fmaf(w, a2[k], s2);
    }
#pragma unroll
    for (int off = 16; off; off >>= 1) {
        s1 += __shfl_xor_sync(0xffffffffu, s1, off);
        s2 += __shfl_xor_sync(0xffffffffu, s2, off);
    }
    if (lane == 0) { g_e1[node] = s1; g_e2[node] = s2; }
}

__global__ void sort_kernel() {
    __shared__ float v[NPAD];
    __shared__ int   p[NPAD];
    int b = blockIdx.x;
    int tid = threadIdx.x;
    const float INF = __int_as_float(0x7f800000);
    for (int i = tid; i < NPAD; i += 1024) {
        v[i] = (i < NN) ? g_e2[b*NN + i] : INF;
        p[i] = i;
    }
    __syncthreads();
    for (int k = 2; k <= NPAD; k <<= 1) {
        for (int j = k >> 1; j > 0; j >>= 1) {
            for (int i = tid; i < NPAD; i += 1024) {
                int ixj = i ^ j;
                if (ixj > i) {
                    bool up = ((i & k) == 0);
                    float a = v[i], c = v[ixj];
                    if (up ? (a > c) : (a < c)) {
                        v[i] = c; v[ixj] = a;
                        int tp = p[i]; p[i] = p[ixj]; p[ixj] = tp;
                    }
                }
            }
            __syncthreads();
        }
    }
    float e2m = v[NN - 1];
    for (int i = tid; i < NPAD; i += 1024) {
        g_e2s[b*NPAD + i] = v[i];
        g_perm[b*NPAD + i] = p[i];
    }
    for (int i = tid; i < NN; i += 1024) {
        float ev = v[i] - e2m;
        g_u1[b*NN + i] = __expf(ev);
        g_u2[b*NN + i] = __expf(0.2f * ev);
    }
}

__global__ void scanA_kernel() {
    int b = blockIdx.x / NCH, c = blockIdx.x % NCH;
    int d = threadIdx.x;
    int k0 = c * CH;
    float sF = 0.f, sB = 0.f;
    for (int k = k0; k < k0 + CH; k++) {
        int pj = g_perm[b*NPAD + k];
        float w = g_Wh[((size_t)b*NN + pj)*DD + d];
        sF = fmaf(g_u2[b*NN + k], w, sF);
        sB = fmaf(g_u1[b*NN + k], w, sB);
    }
    g_chF[(b*NCH + c)*DD + d] = sF;
    g_chB[(b*NCH + c)*DD + d] = sB;
    if (d == 0) {
        float s = 0.f;
        for (int k = k0; k < k0 + CH; k++) s += g_u2[b*NN + k];
        g_chFs[b*NCH + c] = s;
    }
    if (d == 1) {
        float s = 0.f;
        for (int k = k0; k < k0 + CH; k++) s += g_u1[b*NN + k];
        g_chBs[b*NCH + c] = s;
    }
}

__global__ void scanB_kernel() {
    int b = blockIdx.x / NCH, c = blockIdx.x % NCH;
    int d = threadIdx.x;
    float pre = 0.f, suf = 0.f;
    for (int cc = 0; cc < c; cc++)       pre += g_chF[(b*NCH + cc)*DD + d];
    for (int cc = c + 1; cc < NCH; cc++) suf += g_chB[(b*NCH + cc)*DD + d];
    int k0 = c * CH, k1 = k0 + CH;
    size_t rowbase = (size_t)b*NP1;
    float s = pre;
    for (int k = k0; k < k1; k++) {
        g_P2[(rowbase + k)*DD + d] = s;
        int pj = g_perm[b*NPAD + k];
        s = fmaf(g_u2[b*NN + k], g_Wh[((size_t)b*NN + pj)*DD + d], s);
    }
    if (c == NCH - 1) g_P2[(rowbase + NN)*DD + d] = s;
    s = suf;
    for (int k = k1 - 1; k >= k0; k--) {
        g_S1[(rowbase + k + 1)*DD + d] = s;
        int pj = g_perm[b*NPAD + k];
        s = fmaf(g_u1[b*NN + k], g_Wh[((size_t)b*NN + pj)*DD + d], s);
    }
    if (c == 0) g_S1[rowbase*DD + d] = s;
}

__global__ void scanS_kernel() {
    int b = blockIdx.x;
    int t = threadIdx.x;
    if (t < NCH) {
        int c = t;
        float s = 0.f;
        for (int cc = 0; cc < c; cc++) s += g_chFs[b*NCH + cc];
        int k0 = c * CH;
        for (int k = k0; k < k0 + CH; k++) {
            g_P2s[b*NP1 + k] = s;
            s += g_u2[b*NN + k];
        }
        if (c == NCH - 1) g_P2s[b*NP1 + NN] = s;
    } else if (t < 2*NCH) {
        int c = t - NCH;
        float s = 0.f;
        for (int cc = c + 1; cc < NCH; cc++) s += g_chBs[b*NCH + cc];
        int k0 = c * CH;
        for (int k = k0 + CH - 1; k >= k0; k--) {
            g_S1s[b*NP1 + k + 1] = s;
            s += g_u1[b*NN + k];
        }
        if (c == 0) g_S1s[b*NP1] = s;
    }
}

__global__ void combine_kernel() {
    int node = blockIdx.x;
    int b = node / NN;
    int d = threadIdx.x;
    float e1 = g_e1[node];
    const float* e2s = g_e2s + (size_t)b*NPAD;
    float e2m = e2s[NN - 1];
    float v = -e1;
    int lo = 0, hi = NN;
    while (lo < hi) {
        int mid = (lo + hi) >> 1;
        if (e2s[mid] < v) lo = mid + 1; else hi = mid;
    }
    int k = lo;
    float tt = e1 + e2m;
    float m = fmaxf(tt, 0.2f * tt);
    float alpha = __expf(tt - m);
    float beta  = __expf(0.2f * tt - m);
    size_t rb = (size_t)b*NP1 + k;
    float Z = alpha * g_S1s[rb] + beta * g_P2s[rb];
    float inv = 1.0f / Z;
    float num = alpha * g_S1[rb*DD + d] + beta * g_P2[rb*DD + d];
    g_h[(size_t)node*DD + d] = fmaxf(num * inv, 0.f);
}

__global__ void proj_kernel(const float* __restrict__ pw, const float* __restrict__ pb,
                            float* __restrict__ out) {
    __shared__ float hs[DD*HSS];
    int t = threadIdx.x;   // 64
    int base = blockIdx.x * 16;
    for (int kk = t; kk < DD; kk += 64) {
#pragma unroll
        for (int i = 0; i < 16; i++) hs[kk*HSS + i] = g_h[(size_t)(base + i)*DD + kk];
    }
    __syncthreads();
    float acc[16];
    float bv = pb[t];
#pragma unroll
    for (int i = 0; i < 16; i++) acc[i] = bv;
#pragma unroll 4
    for (int k = 0; k < DD; k++) {
        float wv = pw[k*OO + t];
        const float4* hp = (const float4*)(hs + k*HSS);
        fma16(hp[0], hp[1], hp[2], hp[3], wv, acc);
    }
#pragma unroll
    for (int i = 0; i < 16; i++) out[(size_t)(base + i)*OO + t] = acc[i];
}

extern "C" void kernel_launch(void* const* d_in, const int* in_sizes, int n_in,
                              void* d_out, int out_size) {
    const float* coords = (const float*)d_in[0];
    const float* enc_w0 = (const float*)d_in[1];
    const float* enc_b0 = (const float*)d_in[2];
    const float* enc_w1 = (const float*)d_in[3];
    const float* enc_b1 = (const float*)d_in[4];
    const float* gat_W  = (const float*)d_in[5];
    const float* gat_a1 = (const float*)d_in[6];
    const float* gat_a2 = (const float*)d_in[7];
    const float* proj_w = (const float*)d_in[8];
    const float* proj_b = (const float*)d_in[9];
    float* out = (float*)d_out;

    enc_kernel<<<BN/16, 128>>>(coords, enc_w0, enc_b0, enc_w1, enc_b1);
    for (int l = 0; l < NL; l++) {
        wh_kernel<<<BN/16, 128>>>(gat_W + (size_t)l*DD*DD);
        e_kernel<<<BN/8, 256>>>(gat_a1 + l*DD, gat_a2 + l*DD);
        sort_kernel<<<BB, 1024>>>();
        scanA_kernel<<<BB*NCH, 128>>>();
        scanB_kernel<<<BB*NCH, 128>>>();
        scanS_kernel<<<BB, 32>>>();
        combine_kernel<<<BN, 128>>>();
    }
    proj_kernel<<<BN/16, 64>>>(proj_w, proj_b, out);
}

// round 2
// speedup vs baseline: 1.3579x; 1.3579x over previous
#include <cuda_runtime.h>

#define BB 16
#define NN 2000
#define DD 128
#define OO 64
#define NL 3
#define NPAD 2048
#define BN (BB*NN)
#define NCH 125
#define CH 16
#define NP1 (NN+1)
#define HSS 36

__device__ float g_h[BN*DD];
__device__ float g_Wh[BN*DD];
__device__ float g_e1[BN];
__device__ float g_e2[BN];
__device__ float g_e2s[BB*NPAD];
__device__ int   g_perm[BB*NPAD];
__device__ float g_u1[BB*NN];
__device__ float g_u2[BB*NN];
__device__ float g_S1[BB*NP1*DD];
__device__ float g_P2[BB*NP1*DD];
__device__ float g_S1s[BB*NP1];
__device__ float g_P2s[BB*NP1];
__device__ float g_chF[BB*NCH*DD];
__device__ float g_chB[BB*NCH*DD];
__device__ float g_chFs[BB*NCH];
__device__ float g_chBs[BB*NCH];

// ---------- f32x2 packed helpers ----------
__device__ __forceinline__ unsigned long long pk2(float lo, float hi) {
    unsigned long long r;
    asm("mov.b64 %0, {%1, %2};" : "=l"(r)
        : "r"(__float_as_uint(lo)), "r"(__float_as_uint(hi)));
    return r;
}
__device__ __forceinline__ void upk2(unsigned long long v, float& lo, float& hi) {
    unsigned int a, b;
    asm("mov.b64 {%0, %1}, %2;" : "=r"(a), "=r"(b) : "l"(v));
    lo = __uint_as_float(a); hi = __uint_as_float(b);
}
__device__ __forceinline__ unsigned long long fma2(unsigned long long a,
                                                   unsigned long long b,
                                                   unsigned long long c) {
    unsigned long long d;
    asm("fma.rn.f32x2 %0, %1, %2, %3;" : "=l"(d) : "l"(a), "l"(b), "l"(c));
    return d;
}

// 32-node x DD GEMM inner loop: acc (16 x f32x2) += hs[k][0..31] * M[k][t]
__device__ __forceinline__ void gemm32(const float* __restrict__ M, const float* hs,
                                       int t, int ldm, unsigned long long* acc) {
#pragma unroll 2
    for (int k = 0; k < DD; k++) {
        float wv = M[k*ldm + t];
        unsigned long long w2 = pk2(wv, wv);
        const float4* hp = (const float4*)(hs + k*HSS);
#pragma unroll
        for (int q = 0; q < 8; q++) {
            float4 h4 = hp[q];
            acc[2*q]   = fma2(pk2(h4.x, h4.y), w2, acc[2*q]);
            acc[2*q+1] = fma2(pk2(h4.z, h4.w), w2, acc[2*q+1]);
        }
    }
}

// ---------------- encoder ----------------
__global__ void enc_kernel(const float* __restrict__ coords, const float* __restrict__ w0,
                           const float* __restrict__ b0, const float* __restrict__ w1,
                           const float* __restrict__ b1) {
    __shared__ float hs[DD*HSS];
    __shared__ float cxy[64];
    int t = threadIdx.x;              // 128
    int base = blockIdx.x * 32;
    if (t < 64) cxy[t] = coords[(size_t)base*2 + t];
    __syncthreads();
    float w00 = w0[t], w01 = w0[DD + t], bb = b0[t];
#pragma unroll
    for (int i = 0; i < 32; i++)
        hs[t*HSS + i] = fmaxf(fmaf(cxy[2*i], w00, fmaf(cxy[2*i+1], w01, bb)), 0.f);
    __syncthreads();
    unsigned long long acc[16];
    float bv = b1[t];
    unsigned long long b2 = pk2(bv, bv);
#pragma unroll
    for (int q = 0; q < 16; q++) acc[q] = b2;
    gemm32(w1, hs, t, DD, acc);
#pragma unroll
    for (int q = 0; q < 16; q++) {
        float lo, hi; upk2(acc[q], lo, hi);
        int i = 2*q;
        g_h[(size_t)(base + i)*DD + t] = lo;
        g_h[(size_t)(base + i + 1)*DD + t] = hi;
    }
}

// ---------------- Wh = h @ W, fused e1/e2 ----------------
__global__ void whe_kernel(const float* __restrict__ W, const float* __restrict__ a1,
                           const float* __restrict__ a2) {
    __shared__ float hs[DD*HSS];
    __shared__ float red[2][4][32];
    int t = threadIdx.x;              // 128
    int base = blockIdx.x * 32;
#pragma unroll
    for (int i = 0; i < 32; i++) hs[t*HSS + i] = g_h[(size_t)(base + i)*DD + t];
    __syncthreads();
    unsigned long long acc[16];
#pragma unroll
    for (int q = 0; q < 16; q++) acc[q] = 0ull;
    gemm32(W, hs, t, DD, acc);
    float vals[32];
#pragma unroll
    for (int q = 0; q < 16; q++) upk2(acc[q], vals[2*q], vals[2*q+1]);
#pragma unroll
    for (int i = 0; i < 32; i++) g_Wh[(size_t)(base + i)*DD + t] = vals[i];
    // fused e1 = Wh@a1, e2 = Wh@a2 (reduce over t)
    float a1t = a1[t], a2t = a2[t];
    int lane = t & 31, w = t >> 5;
#pragma unroll
    for (int i = 0; i < 32; i++) {
        float s1 = vals[i] * a1t, s2 = vals[i] * a2t;
#pragma unroll
        for (int off = 16; off; off >>= 1) {
            s1 += __shfl_xor_sync(0xffffffffu, s1, off);
            s2 += __shfl_xor_sync(0xffffffffu, s2, off);
        }
        if (lane == 0) { red[0][w][i] = s1; red[1][w][i] = s2; }
    }
    __syncthreads();
    if (t < 64) {
        int which = t >> 5, i = t & 31;
        float s = red[which][0][i] + red[which][1][i] + red[which][2][i] + red[which][3][i];
        if (which == 0) g_e1[base + i] = s; else g_e2[base + i] = s;
    }
}

// ---------------- hybrid bitonic sort (smem for j>=64, shfl for j<=32) ----------------
__global__ void sort_kernel() {
    __shared__ float sv[NPAD];
    __shared__ int   sp[NPAD];
    int b = blockIdx.x, tid = threadIdx.x;      // 1024
    const float INF = __int_as_float(0x7f800000);
    int i0 = 2*tid, i1 = i0 + 1;
    sv[i0] = (i0 < NN) ? g_e2[b*NN + i0] : INF; sp[i0] = i0;
    sv[i1] = (i1 < NN) ? g_e2[b*NN + i1] : INF; sp[i1] = i1;
    __syncthreads();
    for (int k = 2; k <= NPAD; k <<= 1) {
        for (int j = k >> 1; j >= 64; j >>= 1) {
#pragma unroll
            for (int rep = 0; rep < 2; rep++) {
                int i = tid + rep*1024;
                int ixj = i ^ j;
                if (ixj > i) {
                    bool up = ((i & k) == 0);
                    float a = sv[i], c2 = sv[ixj];
                    if (up ? (a > c2) : (a < c2)) {
                        sv[i] = c2; sv[ixj] = a;
                        int tp = sp[i]; sp[i] = sp[ixj]; sp[ixj] = tp;
                    }
                }
            }
            __syncthreads();
        }
        float v0 = sv[i0], v1 = sv[i1];
        int p0 = sp[i0], p1 = sp[i1];
        bool up = ((i0 & k) == 0);
        int jmax = ((k >> 1) < 32) ? (k >> 1) : 32;
        for (int j = jmax; j >= 2; j >>= 1) {
            int dlt = j >> 1;
            float q0 = __shfl_xor_sync(0xffffffffu, v0, dlt);
            int   r0 = __shfl_xor_sync(0xffffffffu, p0, dlt);
            float q1 = __shfl_xor_sync(0xffffffffu, v1, dlt);
            int   r1 = __shfl_xor_sync(0xffffffffu, p1, dlt);
            bool lower = ((tid & dlt) == 0);
            bool tk0 = (lower == up) ? (q0 < v0) : (q0 > v0);
            bool tk1 = (lower == up) ? (q1 < v1) : (q1 > v1);
            if (tk0) { v0 = q0; p0 = r0; }
            if (tk1) { v1 = q1; p1 = r1; }
        }
        if (up ? (v0 > v1) : (v0 < v1)) {
            float tv = v0; v0 = v1; v1 = tv;
            int tp = p0; p0 = p1; p1 = tp;
        }
        sv[i0] = v0; sp[i0] = p0; sv[i1] = v1; sp[i1] = p1;
        __syncthreads();
    }
    float e2m = sv[NN - 1];
#pragma unroll
    for (int rep = 0; rep < 2; rep++) {
        int i = tid + rep*1024;
        g_e2s[b*NPAD + i] = sv[i];
        g_perm[b*NPAD + i] = sp[i];
        if (i < NN) {
            float ev = sv[i] - e2m;
            g_u1[b*NN + i] = __expf(ev);
            g_u2[b*NN + i] = __expf(0.2f * ev);
        }
    }
}

// ---------------- scan pass A: per-chunk (16-elem) sums ----------------
__global__ void scanA_kernel() {
    int b = blockIdx.x / NCH, c = blockIdx.x % NCH;
    int d = threadIdx.x;
    int k0 = c * CH;
    float sF = 0.f, sB = 0.f;
#pragma unroll
    for (int k = k0; k < k0 + CH; k++) {
        int pj = g_perm[b*NPAD + k];
        float w = g_Wh[((size_t)b*NN + pj)*DD + d];
        sF = fmaf(g_u2[b*NN + k], w, sF);
        sB = fmaf(g_u1[b*NN + k], w, sB);
    }
    g_chF[(b*NCH + c)*DD + d] = sF;
    g_chB[(b*NCH + c)*DD + d] = sB;
    if (d == 0) {
        float s = 0.f;
#pragma unroll
        for (int k = k0; k < k0 + CH; k++) s += g_u2[b*NN + k];
        g_chFs[b*NCH + c] = s;
    }
    if (d == 1) {
        float s = 0.f;
#pragma unroll
        for (int k = k0; k < k0 + CH; k++) s += g_u1[b*NN + k];
        g_chBs[b*NCH + c] = s;
    }
}

// ---------------- scan pass C: chunk-level exclusive prefix/suffix (in place) ----------------
__global__ void scanC_kernel() {
    int b = blockIdx.x, d = threadIdx.x;
    float s = 0.f;
    for (int c = 0; c < NCH; c++) {
        int idx = (b*NCH + c)*DD + d;
        float v = g_chF[idx]; g_chF[idx] = s; s += v;
    }
    float s2 = 0.f;
    for (int c = NCH - 1; c >= 0; c--) {
        int idx = (b*NCH + c)*DD + d;
        float v = g_chB[idx]; g_chB[idx] = s2; s2 += v;
    }
    if (d == 0) {
        float ss = 0.f;
        for (int c = 0; c < NCH; c++) {
            float v = g_chFs[b*NCH + c]; g_chFs[b*NCH + c] = ss; ss += v;
        }
    }
    if (d == 1) {
        float ss = 0.f;
        for (int c = NCH - 1; c >= 0; c--) {
            float v = g_chBs[b*NCH + c]; g_chBs[b*NCH + c] = ss; ss += v;
        }
    }
}

// ---------------- scan pass B: expand to full P2 / S1 ----------------
__global__ void scanB_kernel() {
    int b = blockIdx.x / NCH, c = blockIdx.x % NCH;
    int d = threadIdx.x;
    int k0 = c * CH;
    size_t rowbase = (size_t)b*NP1;
    float s = g_chF[(b*NCH + c)*DD + d];
#pragma unroll
    for (int k = k0; k < k0 + CH; k++) {
        g_P2[(rowbase + k)*DD + d] = s;
        int pj = g_perm[b*NPAD + k];
        s = fmaf(g_u2[b*NN + k], g_Wh[((size_t)b*NN + pj)*DD + d], s);
    }
    if (c == NCH - 1) g_P2[(rowbase + NN)*DD + d] = s;
    float s1 = g_chB[(b*NCH + c)*DD + d];
#pragma unroll
    for (int k = k0 + CH - 1; k >= k0; k--) {
        g_S1[(rowbase + k + 1)*DD + d] = s1;
        int pj = g_perm[b*NPAD + k];
        s1 = fmaf(g_u1[b*NN + k], g_Wh[((size_t)b*NN + pj)*DD + d], s1);
    }
    if (c == 0) g_S1[rowbase*DD + d] = s1;
    if (d == 0) {
        float ss = g_chFs[b*NCH + c];
#pragma unroll
        for (int k = k0; k < k0 + CH; k++) {
            g_P2s[b*NP1 + k] = ss;
            ss += g_u2[b*NN + k];
        }
        if (c == NCH - 1) g_P2s[b*NP1 + NN] = ss;
    }
    if (d == 1) {
        float ss = g_chBs[b*NCH + c];
#pragma unroll
        for (int k = k0 + CH - 1; k >= k0; k--) {
            g_S1s[b*NP1 + k + 1] = ss;
            ss += g_u1[b*NN + k];
        }
        if (c == 0) g_S1s[b*NP1] = ss;
    }
}

// ---------------- combine ----------------
__global__ void combine_kernel() {
    int node = blockIdx.x;
    int b = node / NN;
    int d = threadIdx.x;
    float e1 = g_e1[node];
    const float* e2s = g_e2s + (size_t)b*NPAD;
    float e2m = e2s[NN - 1];
    float v = -e1;
    int lo = 0, hi = NN;
    while (lo < hi) {
        int mid = (lo + hi) >> 1;
        if (e2s[mid] < v) lo = mid + 1; else hi = mid;
    }
    int k = lo;
    float tt = e1 + e2m;
    float m = fmaxf(tt, 0.2f * tt);
    float alpha = __expf(tt - m);
    float beta  = __expf(0.2f * tt - m);
    size_t rb = (size_t)b*NP1 + k;
    float Z = alpha * g_S1s[rb] + beta * g_P2s[rb];
    float inv = 1.0f / Z;
    float num = alpha * g_S1[rb*DD + d] + beta * g_P2[rb*DD + d];
    g_h[(size_t)node*DD + d] = fmaxf(num * inv, 0.f);
}

// ---------------- proj ----------------
__global__ void proj_kernel(const float* __restrict__ pw, const float* __restrict__ pb,
                            float* __restrict__ out) {
    __shared__ float hs[DD*HSS];
    int t = threadIdx.x;              // 64
    int base = blockIdx.x * 32;
    for (int kk = t; kk < DD; kk += 64) {
#pragma unroll
        for (int i = 0; i < 32; i++) hs[kk*HSS + i] = g_h[(size_t)(base + i)*DD + kk];
    }
    __syncthreads();
    unsigned long long acc[16];
    float bv = pb[t];
    unsigned long long b2 = pk2(bv, bv);
#pragma unroll
    for (int q = 0; q < 16; q++) acc[q] = b2;
    gemm32(pw, hs, t, OO, acc);
#pragma unroll
    for (int q = 0; q < 16; q++) {
        float lo, hi; upk2(acc[q], lo, hi);
        int i = 2*q;
        out[(size_t)(base + i)*OO + t] = lo;
        out[(size_t)(base + i + 1)*OO + t] = hi;
    }
}

extern "C" void kernel_launch(void* const* d_in, const int* in_sizes, int n_in,
                              void* d_out, int out_size) {
    const float* coords = (const float*)d_in[0];
    const float* enc_w0 = (const float*)d_in[1];
    const float* enc_b0 = (const float*)d_in[2];
    const float* enc_w1 = (const float*)d_in[3];
    const float* enc_b1 = (const float*)d_in[4];
    const float* gat_W  = (const float*)d_in[5];
    const float* gat_a1 = (const float*)d_in[6];
    const float* gat_a2 = (const float*)d_in[7];
    const float* proj_w = (const float*)d_in[8];
    const float* proj_b = (const float*)d_in[9];
    float* out = (float*)d_out;

    enc_kernel<<<BN/32, 128>>>(coords, enc_w0, enc_b0, enc_w1, enc_b1);
    for (int l = 0; l < NL; l++) {
        whe_kernel<<<BN/32, 128>>>(gat_W + (size_t)l*DD*DD, gat_a1 + l*DD, gat_a2 + l*DD);
        sort_kernel<<<BB, 1024>>>();
        scanA_kernel<<<BB*NCH, 128>>>();
        scanC_kernel<<<BB, 128>>>();
        scanB_kernel<<<BB*NCH, 128>>>();
        combine_kernel<<<BN, 128>>>();
    }
    proj_kernel<<<BN/32, 64>>>(proj_w, proj_b, out);
}

// round 3
// speedup vs baseline: 2.1759x; 1.6025x over previous
#include <cuda_runtime.h>

#define BB 16
#define NN 2000
#define DD 128
#define OO 64
#define NL 3
#define NPAD 2048
#define BN (BB*NN)
#define NCH 125
#define CH 16
#define GT 25
#define NP1 (NN+1)
#define HSS 36

__device__ float g_h[BN*DD];
__device__ float g_Wh[BN*DD];
__device__ float g_e1[BN];
__device__ float g_e2[BN];
__device__ float g_e2s[BB*NPAD];
__device__ int   g_perm[BB*NPAD];
__device__ float g_u1[BB*NN];
__device__ float g_u2[BB*NN];
__device__ float g_S1[BB*NP1*DD];
__device__ float g_P2[BB*NP1*DD];
__device__ float g_S1s[BB*NP1];
__device__ float g_P2s[BB*NP1];
__device__ float g_chF[BB*NCH*DD];
__device__ float g_chB[BB*NCH*DD];
__device__ float g_chF2[BB*NCH*DD];
__device__ float g_chB2[BB*NCH*DD];
__device__ float g_chFs[BB*NCH];
__device__ float g_chBs[BB*NCH];
__device__ float g_chFs2[BB*NCH];
__device__ float g_chBs2[BB*NCH];

// ---------- f32x2 packed helpers ----------
__device__ __forceinline__ unsigned long long pk2(float lo, float hi) {
    unsigned long long r;
    asm("mov.b64 %0, {%1, %2};" : "=l"(r)
        : "r"(__float_as_uint(lo)), "r"(__float_as_uint(hi)));
    return r;
}
__device__ __forceinline__ void upk2(unsigned long long v, float& lo, float& hi) {
    unsigned int a, b;
    asm("mov.b64 {%0, %1}, %2;" : "=r"(a), "=r"(b) : "l"(v));
    lo = __uint_as_float(a); hi = __uint_as_float(b);
}
__device__ __forceinline__ unsigned long long fma2(unsigned long long a,
                                                   unsigned long long b,
                                                   unsigned long long c) {
    unsigned long long d;
    asm("fma.rn.f32x2 %0, %1, %2, %3;" : "=l"(d) : "l"(a), "l"(b), "l"(c));
    return d;
}

__device__ __forceinline__ void gemm32(const float* __restrict__ M, const float* hs,
                                       int t, int ldm, unsigned long long* acc) {
#pragma unroll 2
    for (int k = 0; k < DD; k++) {
        float wv = M[k*ldm + t];
        unsigned long long w2 = pk2(wv, wv);
        const float4* hp = (const float4*)(hs + k*HSS);
#pragma unroll
        for (int q = 0; q < 8; q++) {
            float4 h4 = hp[q];
            acc[2*q]   = fma2(pk2(h4.x, h4.y), w2, acc[2*q]);
            acc[2*q+1] = fma2(pk2(h4.z, h4.w), w2, acc[2*q+1]);
        }
    }
}

// combine prelude: per-node (rb, alpha, beta, 1/Z) from previous layer's scans
__device__ __forceinline__ void combine_prelude(int node, int* s_rb, float* s_alpha,
                                                float* s_beta, float* s_inv, int slot) {
    int b = node / NN;
    float e1 = g_e1[node];
    const float* e2s = g_e2s + (size_t)b*NPAD;
    float e2m = e2s[NN - 1];
    float v = -e1;
    int lo = 0, hi = NN;
    while (lo < hi) {
        int mid = (lo + hi) >> 1;
        if (e2s[mid] < v) lo = mid + 1; else hi = mid;
    }
    float tt = e1 + e2m;
    float m = fmaxf(tt, 0.2f * tt);
    float alpha = __expf(tt - m);
    float beta  = __expf(0.2f * tt - m);
    int rb = b*NP1 + lo;
    float Z = alpha * g_S1s[rb] + beta * g_P2s[rb];
    s_rb[slot] = rb; s_alpha[slot] = alpha; s_beta[slot] = beta; s_inv[slot] = 1.0f / Z;
}

// ---------------- encoder ----------------
__global__ void enc_kernel(const float* __restrict__ coords, const float* __restrict__ w0,
                           const float* __restrict__ b0, const float* __restrict__ w1,
                           const float* __restrict__ b1) {
    __shared__ float hs[DD*HSS];
    __shared__ float cxy[64];
    int t = threadIdx.x;
    int base = blockIdx.x * 32;
    if (t < 64) cxy[t] = coords[(size_t)base*2 + t];
    __syncthreads();
    float w00 = w0[t], w01 = w0[DD + t], bb = b0[t];
#pragma unroll
    for (int i = 0; i < 32; i++)
        hs[t*HSS + i] = fmaxf(fmaf(cxy[2*i], w00, fmaf(cxy[2*i+1], w01, bb)), 0.f);
    __syncthreads();
    unsigned long long acc[16];
    float bv = b1[t];
    unsigned long long b2 = pk2(bv, bv);
#pragma unroll
    for (int q = 0; q < 16; q++) acc[q] = b2;
    gemm32(w1, hs, t, DD, acc);
#pragma unroll
    for (int q = 0; q < 16; q++) {
        float lo, hi; upk2(acc[q], lo, hi);
        int i = 2*q;
        g_h[(size_t)(base + i)*DD + t] = lo;
        g_h[(size_t)(base + i + 1)*DD + t] = hi;
    }
}

// ---------------- Wh = h @ W + fused e1/e2 (+ optional fused combine) ----------------
template<bool FUSED>
__global__ void whe_kernel(const float* __restrict__ W, const float* __restrict__ a1,
                           const float* __restrict__ a2) {
    __shared__ float hs[DD*HSS];
    __shared__ float red[2][4][32];
    __shared__ float s_alpha[32], s_beta[32], s_inv[32];
    __shared__ int s_rb[32];
    int t = threadIdx.x;              // 128
    int base = blockIdx.x * 32;
    if (FUSED) {
        if (t < 32) combine_prelude(base + t, s_rb, s_alpha, s_beta, s_inv, t);
        __syncthreads();
#pragma unroll
        for (int i = 0; i < 32; i++) {
            size_t ro = (size_t)s_rb[i]*DD + t;
            float num = s_alpha[i]*g_S1[ro] + s_beta[i]*g_P2[ro];
            hs[t*HSS + i] = fmaxf(num * s_inv[i], 0.f);
        }
    } else {
#pragma unroll
        for (int i = 0; i < 32; i++) hs[t*HSS + i] = g_h[(size_t)(base + i)*DD + t];
    }
    __syncthreads();
    unsigned long long acc[16];
#pragma unroll
    for (int q = 0; q < 16; q++) acc[q] = 0ull;
    gemm32(W, hs, t, DD, acc);
    float vals[32];
#pragma unroll
    for (int q = 0; q < 16; q++) upk2(acc[q], vals[2*q], vals[2*q+1]);
#pragma unroll
    for (int i = 0; i < 32; i++) g_Wh[(size_t)(base + i)*DD + t] = vals[i];
    float a1t = a1[t], a2t = a2[t];
    int lane = t & 31, w = t >> 5;
#pragma unroll
    for (int i = 0; i < 32; i++) {
        float s1 = vals[i] * a1t, s2 = vals[i] * a2t;
#pragma unroll
        for (int off = 16; off; off >>= 1) {
            s1 += __shfl_xor_sync(0xffffffffu, s1, off);
            s2 += __shfl_xor_sync(0xffffffffu, s2, off);
        }
        if (lane == 0) { red[0][w][i] = s1; red[1][w][i] = s2; }
    }
    __syncthreads();
    if (t < 64) {
        int which = t >> 5, i = t & 31;
        float s = red[which][0][i] + red[which][1][i] + red[which][2][i] + red[which][3][i];
        if (which == 0) g_e1[base + i] = s; else g_e2[base + i] = s;
    }
}

// ---------------- hybrid bitonic sort ----------------
__global__ void sort_kernel() {
    __shared__ float sv[NPAD];
    __shared__ int   sp[NPAD];
    int b = blockIdx.x, tid = threadIdx.x;      // 1024
    const float INF = __int_as_float(0x7f800000);
    int i0 = 2*tid, i1 = i0 + 1;
    sv[i0] = (i0 < NN) ? g_e2[b*NN + i0] : INF; sp[i0] = i0;
    sv[i1] = (i1 < NN) ? g_e2[b*NN + i1] : INF; sp[i1] = i1;
    __syncthreads();
    for (int k = 2; k <= NPAD; k <<= 1) {
        for (int j = k >> 1; j >= 64; j >>= 1) {
#pragma unroll
            for (int rep = 0; rep < 2; rep++) {
                int i = tid + rep*1024;
                int ixj = i ^ j;
                if (ixj > i) {
                    bool up = ((i & k) == 0);
                    float a = sv[i], c2 = sv[ixj];
                    if (up ? (a > c2) : (a < c2)) {
                        sv[i] = c2; sv[ixj] = a;
                        int tp = sp[i]; sp[i] = sp[ixj]; sp[ixj] = tp;
                    }
                }
            }
            __syncthreads();
        }
        float v0 = sv[i0], v1 = sv[i1];
        int p0 = sp[i0], p1 = sp[i1];
        bool up = ((i0 & k) == 0);
        int jmax = ((k >> 1) < 32) ? (k >> 1) : 32;
        for (int j = jmax; j >= 2; j >>= 1) {
            int dlt = j >> 1;
            float q0 = __shfl_xor_sync(0xffffffffu, v0, dlt);
            int   r0 = __shfl_xor_sync(0xffffffffu, p0, dlt);
            float q1 = __shfl_xor_sync(0xffffffffu, v1, dlt);
            int   r1 = __shfl_xor_sync(0xffffffffu, p1, dlt);
            bool lower = ((tid & dlt) == 0);
            bool tk0 = (lower == up) ? (q0 < v0) : (q0 > v0);
            bool tk1 = (lower == up) ? (q1 < v1) : (q1 > v1);
            if (tk0) { v0 = q0; p0 = r0; }
            if (tk1) { v1 = q1; p1 = r1; }
        }
        if (up ? (v0 > v1) : (v0 < v1)) {
            float tv = v0; v0 = v1; v1 = tv;
            int tp = p0; p0 = p1; p1 = tp;
        }
        sv[i0] = v0; sp[i0] = p0; sv[i1] = v1; sp[i1] = p1;
        __syncthreads();
    }
    float e2m = sv[NN - 1];
#pragma unroll
    for (int rep = 0; rep < 2; rep++) {
        int i = tid + rep*1024;
        g_e2s[b*NPAD + i] = sv[i];
        g_perm[b*NPAD + i] = sp[i];
        if (i < NN) {
            float ev = sv[i] - e2m;
            g_u1[b*NN + i] = __expf(ev);
            g_u2[b*NN + i] = __expf(0.2f * ev);
        }
    }
}

// ---------------- scanA: per-chunk (16-elem) sums ----------------
__global__ void scanA_kernel() {
    int b = blockIdx.x / NCH, c = blockIdx.x % NCH;
    int d = threadIdx.x;
    int k0 = c * CH;
    float sF = 0.f, sB = 0.f;
#pragma unroll
    for (int k = k0; k < k0 + CH; k++) {
        int pj = g_perm[b*NPAD + k];
        float w = g_Wh[((size_t)b*NN + pj)*DD + d];
        sF = fmaf(g_u2[b*NN + k], w, sF);
        sB = fmaf(g_u1[b*NN + k], w, sB);
    }
    g_chF[(b*NCH + c)*DD + d] = sF;
    g_chB[(b*NCH + c)*DD + d] = sB;
    if (d == 0) {
        float s = 0.f;
#pragma unroll
        for (int k = k0; k < k0 + CH; k++) s += g_u2[b*NN + k];
        g_chFs[b*NCH + c] = s;
    }
    if (d == 1) {
        float s = 0.f;
#pragma unroll
        for (int k = k0; k < k0 + CH; k++) s += g_u1[b*NN + k];
        g_chBs[b*NCH + c] = s;
    }
}

// ---------------- scanC: chunk-level exclusive scans (register-tiled, out-of-place) ----------------
__global__ void scanC_kernel() {       // grid = BB, block = 256
    __shared__ float sFs[NCH], sBs[NCH];
    int b = blockIdx.x, tid = threadIdx.x;
    // stage scalar chunk sums
    if (tid < NCH) sFs[tid] = g_chFs[b*NCH + tid];
    else if (tid >= 128 && tid < 128 + NCH) sBs[tid - 128] = g_chBs[b*NCH + tid - 128];
    __syncthreads();
    if (tid == 0) {
        float s = 0.f;
#pragma unroll 5
        for (int c = 0; c < NCH; c++) { g_chFs2[b*NCH + c] = s; s += sFs[c]; }
    }
    if (tid == 128) {
        float s = 0.f;
#pragma unroll 5
        for (int c = NCH - 1; c >= 0; c--) { g_chBs2[b*NCH + c] = s; s += sBs[c]; }
    }
    // vector scans: thread owns one d-column (no sharing -> registers)
    bool fwd = tid < 128;
    int d = fwd ? tid : tid - 128;
    float s = 0.f;
    float v[GT];
    for (int tile = 0; tile < 5; tile++) {
        int c0 = fwd ? tile*GT : (4 - tile)*GT;
        if (fwd) {
#pragma unroll
            for (int r = 0; r < GT; r++) v[r] = g_chF[(b*NCH + c0 + r)*DD + d];
#pragma unroll
            for (int r = 0; r < GT; r++) { float x = v[r]; v[r] = s; s += x; }
#pragma unroll
            for (int r = 0; r < GT; r++) g_chF2[(b*NCH + c0 + r)*DD + d] = v[r];
        } else {
#pragma unroll
            for (int r = 0; r < GT; r++) v[r] = g_chB[(b*NCH + c0 + r)*DD + d];
#pragma unroll
            for (int r = GT - 1; r >= 0; r--) { float x = v[r]; v[r] = s; s += x; }
#pragma unroll
            for (int r = 0; r < GT; r++) g_chB2[(b*NCH + c0 + r)*DD + d] = v[r];
        }
    }
}

// ---------------- scanB: expand to full P2 / S1 ----------------
__global__ void scanB_kernel() {
    int b = blockIdx.x / NCH, c = blockIdx.x % NCH;
    int d = threadIdx.x;
    int k0 = c * CH;
    size_t rowbase = (size_t)b*NP1;
    float s = g_chF2[(b*NCH + c)*DD + d];
#pragma unroll
    for (int k = k0; k < k0 + CH; k++) {
        g_P2[(rowbase + k)*DD + d] = s;
        int pj = g_perm[b*NPAD + k];
        s = fmaf(g_u2[b*NN + k], g_Wh[((size_t)b*NN + pj)*DD + d], s);
    }
    if (c == NCH - 1) g_P2[(rowbase + NN)*DD + d] = s;
    float s1 = g_chB2[(b*NCH + c)*DD + d];
#pragma unroll
    for (int k = k0 + CH - 1; k >= k0; k--) {
        g_S1[(rowbase + k + 1)*DD + d] = s1;
        int pj = g_perm[b*NPAD + k];
        s1 = fmaf(g_u1[b*NN + k], g_Wh[((size_t)b*NN + pj)*DD + d], s1);
    }
    if (c == 0) g_S1[rowbase*DD + d] = s1;
    if (d == 0) {
        float ss = g_chFs2[b*NCH + c];
#pragma unroll
        for (int k = k0; k < k0 + CH; k++) {
            g_P2s[b*NP1 + k] = ss;
            ss += g_u2[b*NN + k];
        }
        if (c == NCH - 1) g_P2s[b*NP1 + NN] = ss;
    }
    if (d == 1) {
        float ss = g_chBs2[b*NCH + c];
#pragma unroll
        for (int k = k0 + CH - 1; k >= k0; k--) {
            g_S1s[b*NP1 + k + 1] = ss;
            ss += g_u1[b*NN + k];
        }
        if (c == 0) g_S1s[b*NP1] = ss;
    }
}

// ---------------- proj (fused combine) ----------------
__global__ void proj_kernel(const float* __restrict__ pw, const float* __restrict__ pb,
                            float* __restrict__ out) {
    __shared__ float hs[DD*HSS];
    __shared__ float s_alpha[32], s_beta[32], s_inv[32];
    __shared__ int s_rb[32];
    int t = threadIdx.x;              // 64
    int base = blockIdx.x * 32;
    if (t < 32) combine_prelude(base + t, s_rb, s_alpha, s_beta, s_inv, t);
    __syncthreads();
    for (int kk = t; kk < DD; kk += 64) {
#pragma unroll
        for (int i = 0; i < 32; i++) {
            size_t ro = (size_t)s_rb[i]*DD + kk;
            float num = s_alpha[i]*g_S1[ro] + s_beta[i]*g_P2[ro];
            hs[kk*HSS + i] = fmaxf(num * s_inv[i], 0.f);
        }
    }
    __syncthreads();
    unsigned long long acc[16];
    float bv = pb[t];
    unsigned long long b2 = pk2(bv, bv);
#pragma unroll
    for (int q = 0; q < 16; q++) acc[q] = b2;
    gemm32(pw, hs, t, OO, acc);
#pragma unroll
    for (int q = 0; q < 16; q++) {
        float lo, hi; upk2(acc[q], lo, hi);
        int i = 2*q;
        out[(size_t)(base + i)*OO + t] = lo;
        out[(size_t)(base + i + 1)*OO + t] = hi;
    }
}

extern "C" void kernel_launch(void* const* d_in, const int* in_sizes, int n_in,
                              void* d_out, int out_size) {
    const float* coords = (const float*)d_in[0];
    const float* enc_w0 = (const float*)d_in[1];
    const float* enc_b0 = (const float*)d_in[2];
    const float* enc_w1 = (const float*)d_in[3];
    const float* enc_b1 = (const float*)d_in[4];
    const float* gat_W  = (const float*)d_in[5];
    const float* gat_a1 = (const float*)d_in[6];
    const float* gat_a2 = (const float*)d_in[7];
    const float* proj_w = (const float*)d_in[8];
    const float* proj_b = (const float*)d_in[9];
    float* out = (float*)d_out;

    enc_kernel<<<BN/32, 128>>>(coords, enc_w0, enc_b0, enc_w1, enc_b1);
    for (int l = 0; l < NL; l++) {
        if (l == 0)
            whe_kernel<false><<<BN/32, 128>>>(gat_W, gat_a1, gat_a2);
        else
            whe_kernel<true><<<BN/32, 128>>>(gat_W + (size_t)l*DD*DD,
                                             gat_a1 + l*DD, gat_a2 + l*DD);
        sort_kernel<<<BB, 1024>>>();
        scanA_kernel<<<BB*NCH, 128>>>();
        scanC_kernel<<<BB, 256>>>();
        scanB_kernel<<<BB*NCH, 128>>>();
    }
    proj_kernel<<<BN/32, 64>>>(proj_w, proj_b, out);
}